// round 2
// baseline (speedup 1.0000x reference)
#include <cuda_runtime.h>
#include <cuda_bf16.h>
#include <float.h>
#include <math.h>

// Problem constants (fixed-shape problem)
#define NN     50000
#define EEDGE  800000
#define ETOT   (EEDGE + NN)   // edges + self loops
#define FEAT   256            // H*D for layers 1,2

// ---------------- device scratch (no allocations allowed) ----------------
__device__ float g_bufA[(size_t)NN * 256];
__device__ float g_bufB[(size_t)NN * 256];
__device__ float g_es[(size_t)NN * 4];
__device__ float g_ed[(size_t)NN * 4];
__device__ int   g_cnt[NN];
__device__ int   g_cursor[NN];
__device__ int   g_row_ptr[NN + 1];
__device__ int   g_col_src[ETOT];

// ---------------- CSR construction ----------------
__global__ void k_zero_int(int* __restrict__ p, int n) {
    int i = blockIdx.x * blockDim.x + threadIdx.x;
    if (i < n) p[i] = 0;
}

__global__ void k_hist(const int* __restrict__ ei, int E, int n, int* __restrict__ cnt) {
    int i = blockIdx.x * blockDim.x + threadIdx.x;
    int tot = E + n;
    if (i < tot) {
        int d = (i < E) ? ei[E + i] : (i - E);
        atomicAdd(&cnt[d], 1);
    }
}

// single-block exclusive scan over n counts -> row_ptr, cursor
__global__ void k_scan(const int* __restrict__ cnt, int n,
                       int* __restrict__ row_ptr, int* __restrict__ cursor) {
    __shared__ int sh[1024];
    __shared__ int carry;
    const int t = threadIdx.x;
    if (t == 0) carry = 0;
    __syncthreads();
    for (int base = 0; base < n; base += 1024) {
        int i = base + t;
        int v = (i < n) ? cnt[i] : 0;
        sh[t] = v;
        __syncthreads();
        int c0 = carry;
        #pragma unroll
        for (int o = 1; o < 1024; o <<= 1) {
            int add = (t >= o) ? sh[t - o] : 0;
            __syncthreads();
            sh[t] += add;
            __syncthreads();
        }
        int inc = sh[t];
        int exc = inc - v + c0;
        if (i < n) { row_ptr[i] = exc; cursor[i] = exc; }
        __syncthreads();
        if (t == 1023) carry = c0 + sh[1023];
        __syncthreads();
    }
    if (t == 0) row_ptr[n] = carry;
}

__global__ void k_scatter(const int* __restrict__ ei, int E, int n,
                          int* __restrict__ cursor, int* __restrict__ col_src) {
    int i = blockIdx.x * blockDim.x + threadIdx.x;
    int tot = E + n;
    if (i < tot) {
        int s = (i < E) ? ei[i]     : (i - E);
        int d = (i < E) ? ei[E + i] : (i - E);
        int pos = atomicAdd(&cursor[d], 1);
        col_src[pos] = s;
    }
}

// ---------------- GEMM, K=16 (layer 1): h = x @ W1, W1 [16,256] ----------------
__global__ void k_gemm16(const float* __restrict__ X, const float* __restrict__ W,
                         float* __restrict__ O, int nrows) {
    __shared__ float Wsh[16 * 256];
    __shared__ float Xsh[16 * 16];
    const int t = threadIdx.x;  // 256 threads, t = output col
    for (int i = t; i < 16 * 256; i += 256) Wsh[i] = W[i];
    const int r0 = blockIdx.x * 16;
    {
        int r = t >> 4, c = t & 15;
        int rr = r0 + r; if (rr >= nrows) rr = nrows - 1;
        Xsh[t] = X[(size_t)rr * 16 + c];
    }
    __syncthreads();
    float acc[16];
    #pragma unroll
    for (int r = 0; r < 16; r++) acc[r] = 0.f;
    #pragma unroll
    for (int k = 0; k < 16; k++) {
        float w = Wsh[k * 256 + t];
        #pragma unroll
        for (int r = 0; r < 16; r++) acc[r] = fmaf(Xsh[r * 16 + k], w, acc[r]);
    }
    #pragma unroll
    for (int r = 0; r < 16; r++) {
        int rr = r0 + r;
        if (rr < nrows) O[(size_t)rr * 256 + t] = acc[r];
    }
}

// ---------------- GEMM, K=256 (layers 2,3): O[n,M] = X[n,256] @ W[256,M] ----------------
template <int M>
__global__ void k_gemm256(const float* __restrict__ X, const float* __restrict__ W,
                          float* __restrict__ O, int nrows) {
    constexpr int CPT = M / 64;  // cols per thread (4 for M=256, 1 for M=64)
    __shared__ float xs[32][260];
    const int t = threadIdx.x;   // 256 threads
    const int blockRow0 = blockIdx.x * 32;

    for (int i = t; i < 32 * 64; i += 256) {
        int r = i >> 6, c4 = i & 63;
        int rr = blockRow0 + r; if (rr >= nrows) rr = nrows - 1;
        const float4 v = *reinterpret_cast<const float4*>(X + (size_t)rr * 256 + (c4 << 2));
        *reinterpret_cast<float4*>(&xs[r][c4 << 2]) = v;
    }
    __syncthreads();

    const int cx = t & 63;   // col group
    const int ry = t >> 6;   // row group (0..3), 8 rows each

    float acc[8][CPT];
    #pragma unroll
    for (int rr = 0; rr < 8; rr++)
        #pragma unroll
        for (int cc = 0; cc < CPT; cc++) acc[rr][cc] = 0.f;

    float wbuf[4][CPT];
    auto loadW = [&](int k, float wb[4][CPT]) {
        #pragma unroll
        for (int kk = 0; kk < 4; kk++) {
            if (CPT == 4) {
                float4 w4 = *reinterpret_cast<const float4*>(W + (size_t)(k + kk) * M + (cx << 2));
                wb[kk][0] = w4.x; wb[kk][1] = w4.y; wb[kk][2] = w4.z; wb[kk][3] = w4.w;
            } else {
                wb[kk][0] = W[(size_t)(k + kk) * M + cx];
            }
        }
    };
    loadW(0, wbuf);

    #pragma unroll 1
    for (int k = 0; k < 256; k += 4) {
        float wcur[4][CPT];
        #pragma unroll
        for (int kk = 0; kk < 4; kk++)
            #pragma unroll
            for (int cc = 0; cc < CPT; cc++) wcur[kk][cc] = wbuf[kk][cc];
        if (k + 4 < 256) loadW(k + 4, wbuf);

        #pragma unroll
        for (int rr = 0; rr < 8; rr++) {
            float4 xv = *reinterpret_cast<const float4*>(&xs[ry * 8 + rr][k]);
            float xk[4] = {xv.x, xv.y, xv.z, xv.w};
            #pragma unroll
            for (int kk = 0; kk < 4; kk++)
                #pragma unroll
                for (int cc = 0; cc < CPT; cc++)
                    acc[rr][cc] = fmaf(xk[kk], wcur[kk][cc], acc[rr][cc]);
        }
    }

    #pragma unroll
    for (int rr = 0; rr < 8; rr++) {
        int r = blockRow0 + ry * 8 + rr;
        if (r < nrows) {
            #pragma unroll
            for (int cc = 0; cc < CPT; cc++)
                O[(size_t)r * M + cx * CPT + cc] = acc[rr][cc];
        }
    }
}

// ---------------- attention dot products: es/ed [n,H] ----------------
template <int H>
__global__ void k_dots(const float* __restrict__ Hm, const float* __restrict__ As,
                       const float* __restrict__ Ad, float* __restrict__ es,
                       float* __restrict__ ed) {
    const int node = blockIdx.x;
    const int w = threadIdx.x >> 5;  // head
    const int l = threadIdx.x & 31;
    const float* hp = Hm + (size_t)node * (H * 64) + w * 64;
    float s1 = fmaf(hp[l], As[w * 64 + l], hp[l + 32] * As[w * 64 + l + 32]);
    float s2 = fmaf(hp[l], Ad[w * 64 + l], hp[l + 32] * Ad[w * 64 + l + 32]);
    #pragma unroll
    for (int o = 16; o; o >>= 1) {
        s1 += __shfl_xor_sync(0xffffffffu, s1, o);
        s2 += __shfl_xor_sync(0xffffffffu, s2, o);
    }
    if (l == 0) { es[node * H + w] = s1; ed[node * H + w] = s2; }
}

// ---------------- GAT aggregation: one dst node per block ----------------
// blockDim = H*D. Online softmax over incoming edges (chunked), gather h[src].
template <int H, int D, bool ELU>
__global__ void k_agg(const float* __restrict__ Hm, const float* __restrict__ es,
                      const float* __restrict__ ed, const int* __restrict__ row_ptr,
                      const int* __restrict__ col_src, const float* __restrict__ bias,
                      float* __restrict__ out) {
    constexpr int CHUNK = 64;
    constexpr int F = H * D;
    const int node = blockIdx.x;
    const int t = threadIdx.x;
    const int head = t / D;
    const int w = t >> 5, l = t & 31;

    __shared__ float edl[H];
    __shared__ int   src_sh[CHUNK];
    __shared__ float w_sh[CHUNK * H];
    __shared__ float m_sh[H], den_sh[H], scale_sh[H], cmax[H], csum[H];

    const int beg = row_ptr[node];
    const int end = row_ptr[node + 1];

    if (t < H) {
        edl[t] = ed[node * H + t];
        m_sh[t] = -FLT_MAX;
        den_sh[t] = 0.f;
    }
    float acc = 0.f;
    __syncthreads();

    for (int chunk = beg; chunk < end; chunk += CHUNK) {
        const int len = min(CHUNK, end - chunk);

        for (int i = t; i < len; i += F) src_sh[i] = col_src[chunk + i];
        __syncthreads();

        for (int i = t; i < len * H; i += F) {
            int c = i / H, hh = i - c * H;
            float e = es[src_sh[c] * H + hh] + edl[hh];
            w_sh[c * H + hh] = (e > 0.f) ? e : 0.2f * e;
        }
        __syncthreads();

        if (w < H) {
            float mm = -FLT_MAX;
            for (int c = l; c < len; c += 32) mm = fmaxf(mm, w_sh[c * H + w]);
            #pragma unroll
            for (int o = 16; o; o >>= 1) mm = fmaxf(mm, __shfl_xor_sync(0xffffffffu, mm, o));
            if (l == 0) cmax[w] = mm;
        }
        __syncthreads();

        if (t < H) {
            float newm = fmaxf(m_sh[t], cmax[t]);
            float sc = __expf(m_sh[t] - newm);
            scale_sh[t] = sc;
            m_sh[t] = newm;
            den_sh[t] *= sc;
        }
        __syncthreads();

        if (w < H) {
            float ss = 0.f;
            const float newm = m_sh[w];
            for (int c = l; c < len; c += 32) {
                float ex = __expf(w_sh[c * H + w] - newm);
                w_sh[c * H + w] = ex;
                ss += ex;
            }
            #pragma unroll
            for (int o = 16; o; o >>= 1) ss += __shfl_xor_sync(0xffffffffu, ss, o);
            if (l == 0) csum[w] = ss;
        }
        acc *= scale_sh[head];
        __syncthreads();

        if (t < H) den_sh[t] += csum[t];

        #pragma unroll 4
        for (int c = 0; c < len; c++) {
            float wgt = w_sh[c * H + head];
            acc = fmaf(Hm[(size_t)src_sh[c] * F + t], wgt, acc);
        }
        __syncthreads();
    }

    float res = (end > beg) ? (acc / den_sh[head]) : 0.f;
    res += bias[t];
    if (ELU) res = (res > 0.f) ? res : expm1f(res);
    out[(size_t)node * F + t] = res;
}

// ---------------- graph embedding mean ----------------
__global__ void k_zero_f(float* __restrict__ p, int n) {
    int i = blockIdx.x * blockDim.x + threadIdx.x;
    if (i < n) p[i] = 0.f;
}

__global__ void k_mean(const float* __restrict__ node_emb, float* __restrict__ out, int n) {
    const int t = threadIdx.x;  // 64
    float a = 0.f;
    for (int r = blockIdx.x; r < n; r += gridDim.x)
        a += node_emb[(size_t)r * 64 + t];
    atomicAdd(&out[t], a * (1.0f / (float)n));
}

// ---------------- launch ----------------
extern "C" void kernel_launch(void* const* d_in, const int* in_sizes, int n_in,
                              void* d_out, int out_size) {
    const float* x   = (const float*)d_in[0];
    const int*   ei  = (const int*)d_in[1];
    const float* W1  = (const float*)d_in[2];
    const float* a1s = (const float*)d_in[3];
    const float* a1d = (const float*)d_in[4];
    const float* b1  = (const float*)d_in[5];
    const float* W2  = (const float*)d_in[6];
    const float* a2s = (const float*)d_in[7];
    const float* a2d = (const float*)d_in[8];
    const float* b2  = (const float*)d_in[9];
    const float* W3  = (const float*)d_in[10];
    const float* a3s = (const float*)d_in[11];
    const float* a3d = (const float*)d_in[12];
    const float* b3  = (const float*)d_in[13];
    float* out = (float*)d_out;

    const int n = in_sizes[0] / 16;   // 50000
    const int E = in_sizes[1] / 2;    // 800000
    const int tot = E + n;

    float *bufA, *bufB, *es, *ed;
    int *cnt, *cursor, *row_ptr, *col;
    cudaGetSymbolAddress((void**)&bufA, g_bufA);
    cudaGetSymbolAddress((void**)&bufB, g_bufB);
    cudaGetSymbolAddress((void**)&es, g_es);
    cudaGetSymbolAddress((void**)&ed, g_ed);
    cudaGetSymbolAddress((void**)&cnt, g_cnt);
    cudaGetSymbolAddress((void**)&cursor, g_cursor);
    cudaGetSymbolAddress((void**)&row_ptr, g_row_ptr);
    cudaGetSymbolAddress((void**)&col, g_col_src);

    // CSR by dst
    k_zero_int<<<(n + 255) / 256, 256>>>(cnt, n);
    k_hist<<<(tot + 255) / 256, 256>>>(ei, E, n, cnt);
    k_scan<<<1, 1024>>>(cnt, n, row_ptr, cursor);
    k_scatter<<<(tot + 255) / 256, 256>>>(ei, E, n, cursor, col);

    // layer 1: x[n,16] @ W1[16,256]
    k_gemm16<<<(n + 15) / 16, 256>>>(x, W1, bufA, n);
    k_dots<4><<<n, 128>>>(bufA, a1s, a1d, es, ed);
    k_agg<4, 64, true><<<n, 256>>>(bufA, es, ed, row_ptr, col, b1, bufB);

    // layer 2: bufB[n,256] @ W2[256,256]
    k_gemm256<256><<<(n + 31) / 32, 256>>>(bufB, W2, bufA, n);
    k_dots<4><<<n, 128>>>(bufA, a2s, a2d, es, ed);
    k_agg<4, 64, true><<<n, 256>>>(bufA, es, ed, row_ptr, col, b2, bufB);

    // layer 3: bufB[n,256] @ W3[256,64], single head, no elu, direct to d_out
    k_gemm256<64><<<(n + 31) / 32, 256>>>(bufB, W3, bufA, n);
    k_dots<1><<<n, 32>>>(bufA, a3s, a3d, es, ed);
    k_agg<1, 64, false><<<n, 64>>>(bufA, es, ed, row_ptr, col, b3, out);

    // graph embedding = mean over nodes
    k_zero_f<<<1, 64>>>(out + (size_t)n * 64, 64);
    k_mean<<<256, 64>>>(out, out + (size_t)n * 64, n);
}

// round 3
// speedup vs baseline: 1.3128x; 1.3128x over previous
#include <cuda_runtime.h>
#include <cuda_bf16.h>
#include <float.h>
#include <math.h>

#define NN     50000
#define EEDGE  800000
#define ETOT   (EEDGE + NN)

typedef unsigned long long ull;

// ---------------- device scratch ----------------
__device__ float g_bufA[(size_t)NN * 256];
__device__ float g_bufB[(size_t)NN * 256];
__device__ float g_es[(size_t)NN * 4];
__device__ float g_ed[(size_t)NN * 4];
__device__ float g_den[(size_t)NN * 4];
__device__ float g_alpha[(size_t)ETOT * 4];
__device__ int   g_cnt[NN];
__device__ int   g_cursor[NN];
__device__ int   g_row_ptr[NN + 1];
__device__ int   g_col_src[ETOT];
__device__ int   g_part[64];

// ---------------- f32x2 helpers ----------------
__device__ __forceinline__ ull fma2(ull a, ull b, ull c) {
    ull d;
    asm("fma.rn.f32x2 %0, %1, %2, %3;" : "=l"(d) : "l"(a), "l"(b), "l"(c));
    return d;
}
__device__ __forceinline__ ull dup2(float x) {
    ull d;
    asm("mov.b64 %0, {%1, %1};" : "=l"(d) : "f"(x));
    return d;
}
__device__ __forceinline__ void unpack2(ull v, float& lo, float& hi) {
    asm("mov.b64 {%0, %1}, %2;" : "=f"(lo), "=f"(hi) : "l"(v));
}

// ---------------- CSR construction ----------------
__global__ void k_zero_int(int* __restrict__ p, int n) {
    int i = blockIdx.x * blockDim.x + threadIdx.x;
    if (i < n) p[i] = 0;
}

__global__ void k_hist(const int* __restrict__ ei, int E, int n, int* __restrict__ cnt) {
    int i = blockIdx.x * blockDim.x + threadIdx.x;
    int tot = E + n;
    if (i < tot) {
        int d = (i < E) ? ei[E + i] : (i - E);
        atomicAdd(&cnt[d], 1);
    }
}

// stage 1: per-block inclusive scan -> row_ptr (temp), block totals -> part
__global__ void k_scan1(const int* __restrict__ cnt, int n,
                        int* __restrict__ incl, int* __restrict__ part) {
    __shared__ int sh[1024];
    const int t = threadIdx.x;
    const int i = blockIdx.x * 1024 + t;
    int v = (i < n) ? cnt[i] : 0;
    sh[t] = v;
    __syncthreads();
    #pragma unroll
    for (int o = 1; o < 1024; o <<= 1) {
        int add = (t >= o) ? sh[t - o] : 0;
        __syncthreads();
        sh[t] += add;
        __syncthreads();
    }
    if (i < n) incl[i] = sh[t];
    if (t == 1023) part[blockIdx.x] = sh[1023];
}

// stage 2: exclusive scan of block totals (single warp)
__global__ void k_scan2(int* __restrict__ p, int B) {
    const int t = threadIdx.x;  // 32
    int carry = 0;
    for (int base = 0; base < B; base += 32) {
        int i = base + t;
        int v = (i < B) ? p[i] : 0;
        int x = v;
        #pragma unroll
        for (int o = 1; o < 32; o <<= 1) {
            int y = __shfl_up_sync(0xffffffffu, x, o);
            if (t >= o) x += y;
        }
        if (i < B) p[i] = x - v + carry;
        carry += __shfl_sync(0xffffffffu, x, 31);
    }
}

// stage 3: finalize exclusive row_ptr + cursor
__global__ void k_scan3(const int* __restrict__ cnt, int n,
                        int* __restrict__ row_ptr, int* __restrict__ cursor,
                        const int* __restrict__ part) {
    const int i = blockIdx.x * 1024 + threadIdx.x;
    if (i < n) {
        int incl = row_ptr[i];
        int c = cnt[i];
        int exc = incl - c + part[blockIdx.x];
        row_ptr[i] = exc;
        cursor[i] = exc;
        if (i == n - 1) row_ptr[n] = exc + c;
    }
}

__global__ void k_scatter(const int* __restrict__ ei, int E, int n,
                          int* __restrict__ cursor, int* __restrict__ col_src) {
    int i = blockIdx.x * blockDim.x + threadIdx.x;
    int tot = E + n;
    if (i < tot) {
        int s = (i < E) ? ei[i]     : (i - E);
        int d = (i < E) ? ei[E + i] : (i - E);
        int pos = atomicAdd(&cursor[d], 1);
        col_src[pos] = s;
    }
}

// ---------------- GEMM, K=16 (layer 1) ----------------
__global__ void k_gemm16(const float* __restrict__ X, const float* __restrict__ W,
                         float* __restrict__ O, int nrows) {
    __shared__ float Wsh[16 * 256];
    __shared__ float Xsh[16 * 16];
    const int t = threadIdx.x;
    for (int i = t; i < 16 * 256; i += 256) Wsh[i] = W[i];
    const int r0 = blockIdx.x * 16;
    {
        int r = t >> 4, c = t & 15;
        int rr = r0 + r; if (rr >= nrows) rr = nrows - 1;
        Xsh[t] = X[(size_t)rr * 16 + c];
    }
    __syncthreads();
    float acc[16];
    #pragma unroll
    for (int r = 0; r < 16; r++) acc[r] = 0.f;
    #pragma unroll
    for (int k = 0; k < 16; k++) {
        float w = Wsh[k * 256 + t];
        #pragma unroll
        for (int r = 0; r < 16; r++) acc[r] = fmaf(Xsh[r * 16 + k], w, acc[r]);
    }
    #pragma unroll
    for (int r = 0; r < 16; r++) {
        int rr = r0 + r;
        if (rr < nrows) O[(size_t)rr * 256 + t] = acc[r];
    }
}

// ---------------- GEMM K=256, M=256 with packed fp32x2 ----------------
__global__ void k_gemm256_f2(const float* __restrict__ X, const float* __restrict__ W,
                             float* __restrict__ O, int nrows) {
    __shared__ float xs[32][260];
    const int t = threadIdx.x;        // 256
    const int r0 = blockIdx.x * 32;

    for (int i = t; i < 32 * 64; i += 256) {
        int r = i >> 6, c4 = i & 63;
        int rr = r0 + r; if (rr >= nrows) rr = nrows - 1;
        *reinterpret_cast<float4*>(&xs[r][c4 << 2]) =
            *reinterpret_cast<const float4*>(X + (size_t)rr * 256 + (c4 << 2));
    }
    __syncthreads();

    const int cx = t & 63;            // 4 cols (2 packed)
    const int ry = t >> 6;            // 4 groups x 8 rows

    ull acc[8][2];
    #pragma unroll
    for (int r = 0; r < 8; r++) { acc[r][0] = 0ull; acc[r][1] = 0ull; }

    ull wbuf[4][2];
    #pragma unroll
    for (int kk = 0; kk < 4; kk++) {
        ulonglong2 wv = *(reinterpret_cast<const ulonglong2*>(W + (size_t)kk * 256) + cx);
        wbuf[kk][0] = wv.x; wbuf[kk][1] = wv.y;
    }

    #pragma unroll 1
    for (int k = 0; k < 256; k += 4) {
        ull wc[4][2];
        #pragma unroll
        for (int kk = 0; kk < 4; kk++) { wc[kk][0] = wbuf[kk][0]; wc[kk][1] = wbuf[kk][1]; }
        if (k + 4 < 256) {
            #pragma unroll
            for (int kk = 0; kk < 4; kk++) {
                ulonglong2 wv = *(reinterpret_cast<const ulonglong2*>(W + (size_t)(k + 4 + kk) * 256) + cx);
                wbuf[kk][0] = wv.x; wbuf[kk][1] = wv.y;
            }
        }
        #pragma unroll
        for (int rr = 0; rr < 8; rr++) {
            float4 xv = *reinterpret_cast<const float4*>(&xs[ry * 8 + rr][k]);
            ull x0 = dup2(xv.x), x1 = dup2(xv.y), x2 = dup2(xv.z), x3 = dup2(xv.w);
            acc[rr][0] = fma2(x0, wc[0][0], acc[rr][0]);
            acc[rr][1] = fma2(x0, wc[0][1], acc[rr][1]);
            acc[rr][0] = fma2(x1, wc[1][0], acc[rr][0]);
            acc[rr][1] = fma2(x1, wc[1][1], acc[rr][1]);
            acc[rr][0] = fma2(x2, wc[2][0], acc[rr][0]);
            acc[rr][1] = fma2(x2, wc[2][1], acc[rr][1]);
            acc[rr][0] = fma2(x3, wc[3][0], acc[rr][0]);
            acc[rr][1] = fma2(x3, wc[3][1], acc[rr][1]);
        }
    }

    #pragma unroll
    for (int rr = 0; rr < 8; rr++) {
        int r = r0 + ry * 8 + rr;
        if (r < nrows) {
            float4 v;
            unpack2(acc[rr][0], v.x, v.y);
            unpack2(acc[rr][1], v.z, v.w);
            *reinterpret_cast<float4*>(O + (size_t)r * 256 + (cx << 2)) = v;
        }
    }
}

// ---------------- GEMM K=256, M=64 with packed fp32x2 ----------------
__global__ void k_gemm64_f2(const float* __restrict__ X, const float* __restrict__ W,
                            float* __restrict__ O, int nrows) {
    __shared__ float xs[32][260];
    const int t = threadIdx.x;        // 256
    const int r0 = blockIdx.x * 32;

    for (int i = t; i < 32 * 64; i += 256) {
        int r = i >> 6, c4 = i & 63;
        int rr = r0 + r; if (rr >= nrows) rr = nrows - 1;
        *reinterpret_cast<float4*>(&xs[r][c4 << 2]) =
            *reinterpret_cast<const float4*>(X + (size_t)rr * 256 + (c4 << 2));
    }
    __syncthreads();

    const int cx = t & 15;            // 4 cols (2 packed)
    const int ry = t >> 4;            // 16 groups x 2 rows

    ull acc[2][2];
    acc[0][0] = acc[0][1] = acc[1][0] = acc[1][1] = 0ull;

    ull wbuf[4][2];
    #pragma unroll
    for (int kk = 0; kk < 4; kk++) {
        ulonglong2 wv = *(reinterpret_cast<const ulonglong2*>(W + (size_t)kk * 64) + cx);
        wbuf[kk][0] = wv.x; wbuf[kk][1] = wv.y;
    }

    #pragma unroll 1
    for (int k = 0; k < 256; k += 4) {
        ull wc[4][2];
        #pragma unroll
        for (int kk = 0; kk < 4; kk++) { wc[kk][0] = wbuf[kk][0]; wc[kk][1] = wbuf[kk][1]; }
        if (k + 4 < 256) {
            #pragma unroll
            for (int kk = 0; kk < 4; kk++) {
                ulonglong2 wv = *(reinterpret_cast<const ulonglong2*>(W + (size_t)(k + 4 + kk) * 64) + cx);
                wbuf[kk][0] = wv.x; wbuf[kk][1] = wv.y;
            }
        }
        #pragma unroll
        for (int rr = 0; rr < 2; rr++) {
            float4 xv = *reinterpret_cast<const float4*>(&xs[ry * 2 + rr][k]);
            ull x0 = dup2(xv.x), x1 = dup2(xv.y), x2 = dup2(xv.z), x3 = dup2(xv.w);
            acc[rr][0] = fma2(x0, wc[0][0], acc[rr][0]);
            acc[rr][1] = fma2(x0, wc[0][1], acc[rr][1]);
            acc[rr][0] = fma2(x1, wc[1][0], acc[rr][0]);
            acc[rr][1] = fma2(x1, wc[1][1], acc[rr][1]);
            acc[rr][0] = fma2(x2, wc[2][0], acc[rr][0]);
            acc[rr][1] = fma2(x2, wc[2][1], acc[rr][1]);
            acc[rr][0] = fma2(x3, wc[3][0], acc[rr][0]);
            acc[rr][1] = fma2(x3, wc[3][1], acc[rr][1]);
        }
    }

    #pragma unroll
    for (int rr = 0; rr < 2; rr++) {
        int r = r0 + ry * 2 + rr;
        if (r < nrows) {
            float4 v;
            unpack2(acc[rr][0], v.x, v.y);
            unpack2(acc[rr][1], v.z, v.w);
            *reinterpret_cast<float4*>(O + (size_t)r * 64 + (cx << 2)) = v;
        }
    }
}

// ---------------- attention dot products ----------------
template <int H>
__global__ void k_dots(const float* __restrict__ Hm, const float* __restrict__ As,
                       const float* __restrict__ Ad, float* __restrict__ es,
                       float* __restrict__ ed) {
    const int node = blockIdx.x;
    const int w = threadIdx.x >> 5;
    const int l = threadIdx.x & 31;
    const float* hp = Hm + (size_t)node * (H * 64) + w * 64;
    float s1 = fmaf(hp[l], As[w * 64 + l], hp[l + 32] * As[w * 64 + l + 32]);
    float s2 = fmaf(hp[l], Ad[w * 64 + l], hp[l + 32] * Ad[w * 64 + l + 32]);
    #pragma unroll
    for (int o = 16; o; o >>= 1) {
        s1 += __shfl_xor_sync(0xffffffffu, s1, o);
        s2 += __shfl_xor_sync(0xffffffffu, s2, o);
    }
    if (l == 0) { es[node * H + w] = s1; ed[node * H + w] = s2; }
}

// ---------------- softmax prep: per-edge exp weights (CSR order) + den ----------------
template <int H>
__global__ void k_prep(const float* __restrict__ es, const float* __restrict__ ed,
                       const int* __restrict__ row_ptr, const int* __restrict__ col,
                       float* __restrict__ alpha, float* __restrict__ den) {
    const int node = blockIdx.x;
    const int w = threadIdx.x >> 5;   // head
    const int l = threadIdx.x & 31;
    const int beg = row_ptr[node];
    const int end = row_ptr[node + 1];
    const float edl = ed[node * H + w];

    float mm = -FLT_MAX;
    for (int c = beg + l; c < end; c += 32) {
        float e = es[col[c] * H + w] + edl;
        e = (e > 0.f) ? e : 0.2f * e;
        mm = fmaxf(mm, e);
    }
    #pragma unroll
    for (int o = 16; o; o >>= 1) mm = fmaxf(mm, __shfl_xor_sync(0xffffffffu, mm, o));

    float ss = 0.f;
    for (int c = beg + l; c < end; c += 32) {
        float e = es[col[c] * H + w] + edl;
        e = (e > 0.f) ? e : 0.2f * e;
        float ex = __expf(e - mm);
        alpha[(size_t)c * H + w] = ex;
        ss += ex;
    }
    #pragma unroll
    for (int o = 16; o; o >>= 1) ss += __shfl_xor_sync(0xffffffffu, ss, o);
    if (l == 0) den[node * H + w] = ss;
}

// ---------------- aggregation: pure gather-FMA with precomputed weights ----------------
template <int H, bool ELU>
__global__ void k_agg2(const float* __restrict__ Hm, const int* __restrict__ row_ptr,
                       const int* __restrict__ col, const float* __restrict__ alpha,
                       const float* __restrict__ den, const float* __restrict__ bias,
                       float* __restrict__ out) {
    constexpr int F = H * 64;
    constexpr int CH = 128;
    const int node = blockIdx.x;
    const int t = threadIdx.x;
    const int head = t >> 6;

    __shared__ int   ssrc[CH];
    __shared__ float sa[CH * H];
    __shared__ float sinv[H];

    const int beg = row_ptr[node];
    const int end = row_ptr[node + 1];

    if (t < H) sinv[t] = 1.0f / den[node * H + t];

    float a0 = 0.f, a1 = 0.f, a2 = 0.f, a3 = 0.f;
    float a4 = 0.f, a5 = 0.f, a6 = 0.f, a7 = 0.f;

    for (int ch = beg; ch < end; ch += CH) {
        const int len = min(CH, end - ch);
        __syncthreads();
        for (int i = t; i < len; i += F) ssrc[i] = col[ch + i];
        for (int i = t; i < len * H; i += F) sa[i] = alpha[(size_t)ch * H + i];
        __syncthreads();

        int c = 0;
        for (; c + 8 <= len; c += 8) {
            int s0 = ssrc[c],     s1 = ssrc[c + 1], s2 = ssrc[c + 2], s3 = ssrc[c + 3];
            int s4 = ssrc[c + 4], s5 = ssrc[c + 5], s6 = ssrc[c + 6], s7 = ssrc[c + 7];
            float w0 = sa[(c    ) * H + head], w1 = sa[(c + 1) * H + head];
            float w2 = sa[(c + 2) * H + head], w3 = sa[(c + 3) * H + head];
            float w4 = sa[(c + 4) * H + head], w5 = sa[(c + 5) * H + head];
            float w6 = sa[(c + 6) * H + head], w7 = sa[(c + 7) * H + head];
            a0 = fmaf(Hm[(size_t)s0 * F + t], w0, a0);
            a1 = fmaf(Hm[(size_t)s1 * F + t], w1, a1);
            a2 = fmaf(Hm[(size_t)s2 * F + t], w2, a2);
            a3 = fmaf(Hm[(size_t)s3 * F + t], w3, a3);
            a4 = fmaf(Hm[(size_t)s4 * F + t], w4, a4);
            a5 = fmaf(Hm[(size_t)s5 * F + t], w5, a5);
            a6 = fmaf(Hm[(size_t)s6 * F + t], w6, a6);
            a7 = fmaf(Hm[(size_t)s7 * F + t], w7, a7);
        }
        for (; c < len; c++)
            a0 = fmaf(Hm[(size_t)ssrc[c] * F + t], sa[c * H + head], a0);
    }

    float res = ((a0 + a1) + (a2 + a3)) + ((a4 + a5) + (a6 + a7));
    res = res * sinv[head] + bias[t];
    if (ELU) res = (res > 0.f) ? res : expm1f(res);
    out[(size_t)node * F + t] = res;
}

// ---------------- graph embedding mean ----------------
__global__ void k_zero_f(float* __restrict__ p, int n) {
    int i = blockIdx.x * blockDim.x + threadIdx.x;
    if (i < n) p[i] = 0.f;
}

__global__ void k_mean(const float* __restrict__ node_emb, float* __restrict__ out, int n) {
    const int t = threadIdx.x;  // 64
    float a = 0.f;
    for (int r = blockIdx.x; r < n; r += gridDim.x)
        a += node_emb[(size_t)r * 64 + t];
    atomicAdd(&out[t], a * (1.0f / (float)n));
}

// ---------------- launch ----------------
extern "C" void kernel_launch(void* const* d_in, const int* in_sizes, int n_in,
                              void* d_out, int out_size) {
    const float* x   = (const float*)d_in[0];
    const int*   ei  = (const int*)d_in[1];
    const float* W1  = (const float*)d_in[2];
    const float* a1s = (const float*)d_in[3];
    const float* a1d = (const float*)d_in[4];
    const float* b1  = (const float*)d_in[5];
    const float* W2  = (const float*)d_in[6];
    const float* a2s = (const float*)d_in[7];
    const float* a2d = (const float*)d_in[8];
    const float* b2  = (const float*)d_in[9];
    const float* W3  = (const float*)d_in[10];
    const float* a3s = (const float*)d_in[11];
    const float* a3d = (const float*)d_in[12];
    const float* b3  = (const float*)d_in[13];
    float* out = (float*)d_out;

    const int n = in_sizes[0] / 16;   // 50000
    const int E = in_sizes[1] / 2;    // 800000
    const int tot = E + n;
    const int B = (n + 1023) / 1024;

    float *bufA, *bufB, *es, *ed, *den, *alpha;
    int *cnt, *cursor, *row_ptr, *col, *part;
    cudaGetSymbolAddress((void**)&bufA, g_bufA);
    cudaGetSymbolAddress((void**)&bufB, g_bufB);
    cudaGetSymbolAddress((void**)&es, g_es);
    cudaGetSymbolAddress((void**)&ed, g_ed);
    cudaGetSymbolAddress((void**)&den, g_den);
    cudaGetSymbolAddress((void**)&alpha, g_alpha);
    cudaGetSymbolAddress((void**)&cnt, g_cnt);
    cudaGetSymbolAddress((void**)&cursor, g_cursor);
    cudaGetSymbolAddress((void**)&row_ptr, g_row_ptr);
    cudaGetSymbolAddress((void**)&col, g_col_src);
    cudaGetSymbolAddress((void**)&part, g_part);

    // CSR by dst
    k_zero_int<<<(n + 255) / 256, 256>>>(cnt, n);
    k_hist<<<(tot + 255) / 256, 256>>>(ei, E, n, cnt);
    k_scan1<<<B, 1024>>>(cnt, n, row_ptr, part);
    k_scan2<<<1, 32>>>(part, B);
    k_scan3<<<B, 1024>>>(cnt, n, row_ptr, cursor, part);
    k_scatter<<<(tot + 255) / 256, 256>>>(ei, E, n, cursor, col);

    // layer 1
    k_gemm16<<<(n + 15) / 16, 256>>>(x, W1, bufA, n);
    k_dots<4><<<n, 128>>>(bufA, a1s, a1d, es, ed);
    k_prep<4><<<n, 128>>>(es, ed, row_ptr, col, alpha, den);
    k_agg2<4, true><<<n, 256>>>(bufA, row_ptr, col, alpha, den, b1, bufB);

    // layer 2
    k_gemm256_f2<<<(n + 31) / 32, 256>>>(bufB, W2, bufA, n);
    k_dots<4><<<n, 128>>>(bufA, a2s, a2d, es, ed);
    k_prep<4><<<n, 128>>>(es, ed, row_ptr, col, alpha, den);
    k_agg2<4, true><<<n, 256>>>(bufA, row_ptr, col, alpha, den, b2, bufB);

    // layer 3
    k_gemm64_f2<<<(n + 31) / 32, 256>>>(bufB, W3, bufA, n);
    k_dots<1><<<n, 32>>>(bufA, a3s, a3d, es, ed);
    k_prep<1><<<n, 32>>>(es, ed, row_ptr, col, alpha, den);
    k_agg2<1, false><<<n, 64>>>(bufA, row_ptr, col, alpha, den, b3, out);

    // graph embedding
    k_zero_f<<<1, 64>>>(out + (size_t)n * 64, 64);
    k_mean<<<256, 64>>>(out, out + (size_t)n * 64, n);
}

// round 4
// speedup vs baseline: 1.3456x; 1.0249x over previous
#include <cuda_runtime.h>
#include <cuda_bf16.h>
#include <float.h>
#include <math.h>

#define NN     50000
#define EEDGE  800000
#define ETOT   (EEDGE + NN)

typedef unsigned long long ull;

// ---------------- device scratch ----------------
__device__ float g_bufA[(size_t)NN * 256];
__device__ float g_bufB[(size_t)NN * 256];
__device__ float g_es[(size_t)NN * 4];
__device__ float g_ed[(size_t)NN * 4];
__device__ float g_den[(size_t)NN * 4];
__device__ float g_alpha[4][(size_t)ETOT];   // head-major
__device__ int   g_cnt[NN];
__device__ int   g_cursor[NN];
__device__ int   g_row_ptr[NN + 1];
__device__ int   g_col_src[ETOT];
__device__ int   g_part[64];

// ---------------- tf32 helpers ----------------
__device__ __forceinline__ unsigned tf32h(float x) {
    unsigned u;
    asm("cvt.rna.tf32.f32 %0, %1;" : "=r"(u) : "f"(x));
    return u;
}
__device__ __forceinline__ void mma_tf32(float* c, const unsigned* a, const unsigned* b) {
    asm volatile("mma.sync.aligned.m16n8k8.row.col.f32.tf32.tf32.f32 "
        "{%0,%1,%2,%3}, {%4,%5,%6,%7}, {%8,%9}, {%0,%1,%2,%3};"
        : "+f"(c[0]), "+f"(c[1]), "+f"(c[2]), "+f"(c[3])
        : "r"(a[0]), "r"(a[1]), "r"(a[2]), "r"(a[3]), "r"(b[0]), "r"(b[1]));
}

// ---------------- CSR construction ----------------
__global__ void k_zero_int(int* __restrict__ p, int n) {
    int i = blockIdx.x * blockDim.x + threadIdx.x;
    if (i < n) p[i] = 0;
}

__global__ void k_hist(const int* __restrict__ ei, int E, int n, int* __restrict__ cnt) {
    int i = blockIdx.x * blockDim.x + threadIdx.x;
    int tot = E + n;
    if (i < tot) {
        int d = (i < E) ? ei[E + i] : (i - E);
        atomicAdd(&cnt[d], 1);
    }
}

__global__ void k_scan1(const int* __restrict__ cnt, int n,
                        int* __restrict__ incl, int* __restrict__ part) {
    __shared__ int sh[1024];
    const int t = threadIdx.x;
    const int i = blockIdx.x * 1024 + t;
    int v = (i < n) ? cnt[i] : 0;
    sh[t] = v;
    __syncthreads();
    #pragma unroll
    for (int o = 1; o < 1024; o <<= 1) {
        int add = (t >= o) ? sh[t - o] : 0;
        __syncthreads();
        sh[t] += add;
        __syncthreads();
    }
    if (i < n) incl[i] = sh[t];
    if (t == 1023) part[blockIdx.x] = sh[1023];
}

__global__ void k_scan2(int* __restrict__ p, int B) {
    const int t = threadIdx.x;
    int carry = 0;
    for (int base = 0; base < B; base += 32) {
        int i = base + t;
        int v = (i < B) ? p[i] : 0;
        int x = v;
        #pragma unroll
        for (int o = 1; o < 32; o <<= 1) {
            int y = __shfl_up_sync(0xffffffffu, x, o);
            if (t >= o) x += y;
        }
        if (i < B) p[i] = x - v + carry;
        carry += __shfl_sync(0xffffffffu, x, 31);
    }
}

__global__ void k_scan3(const int* __restrict__ cnt, int n,
                        int* __restrict__ row_ptr, int* __restrict__ cursor,
                        const int* __restrict__ part) {
    const int i = blockIdx.x * 1024 + threadIdx.x;
    if (i < n) {
        int incl = row_ptr[i];
        int c = cnt[i];
        int exc = incl - c + part[blockIdx.x];
        row_ptr[i] = exc;
        cursor[i] = exc;
        if (i == n - 1) row_ptr[n] = exc + c;
    }
}

__global__ void k_scatter(const int* __restrict__ ei, int E, int n,
                          int* __restrict__ cursor, int* __restrict__ col_src) {
    int i = blockIdx.x * blockDim.x + threadIdx.x;
    int tot = E + n;
    if (i < tot) {
        int s = (i < E) ? ei[i]     : (i - E);
        int d = (i < E) ? ei[E + i] : (i - E);
        int pos = atomicAdd(&cursor[d], 1);
        col_src[pos] = s;
    }
}

// ---------------- GEMM, K=16 (layer 1) ----------------
__global__ void k_gemm16(const float* __restrict__ X, const float* __restrict__ W,
                         float* __restrict__ O, int nrows) {
    __shared__ float Wsh[16 * 256];
    __shared__ float Xsh[16 * 16];
    const int t = threadIdx.x;
    for (int i = t; i < 16 * 256; i += 256) Wsh[i] = W[i];
    const int r0 = blockIdx.x * 16;
    {
        int r = t >> 4, c = t & 15;
        int rr = r0 + r; if (rr >= nrows) rr = nrows - 1;
        Xsh[t] = X[(size_t)rr * 16 + c];
    }
    __syncthreads();
    float acc[16];
    #pragma unroll
    for (int r = 0; r < 16; r++) acc[r] = 0.f;
    #pragma unroll
    for (int k = 0; k < 16; k++) {
        float w = Wsh[k * 256 + t];
        #pragma unroll
        for (int r = 0; r < 16; r++) acc[r] = fmaf(Xsh[r * 16 + k], w, acc[r]);
    }
    #pragma unroll
    for (int r = 0; r < 16; r++) {
        int rr = r0 + r;
        if (rr < nrows) O[(size_t)rr * 256 + t] = acc[r];
    }
}

// ---------------- tf32x3 tensor-core GEMM: O[n,NT] = X[n,256] @ W[256,NT] ----------------
// block: 256 thr (8 warps 4x2), tile 128 rows x 64 cols, K chunked by 32.
template <int NT>
__global__ void __launch_bounds__(256)
k_gemm_tf32(const float* __restrict__ X, const float* __restrict__ W,
            float* __restrict__ O, int nrows) {
    __shared__ __align__(16) float Xs[128][36];
    __shared__ __align__(16) float Ws[32][72];

    const int t = threadIdx.x;
    const int lane = t & 31;
    const int w = t >> 5;
    const int warp_m = w >> 1;       // 0..3
    const int warp_n = w & 1;        // 0..1
    const int lr = lane >> 2;        // 0..7
    const int lc = lane & 3;         // 0..3
    const int r0 = blockIdx.x * 128;
    const int n0 = blockIdx.y * 64;

    float acc[2][4][4];
    #pragma unroll
    for (int mt = 0; mt < 2; mt++)
        #pragma unroll
        for (int nt = 0; nt < 4; nt++)
            #pragma unroll
            for (int i = 0; i < 4; i++) acc[mt][nt][i] = 0.f;

    for (int k0 = 0; k0 < 256; k0 += 32) {
        __syncthreads();
        #pragma unroll
        for (int j = 0; j < 4; j++) {
            int idx = t + j * 256;
            int row = idx >> 3, c4 = idx & 7;
            int rr = r0 + row; if (rr >= nrows) rr = nrows - 1;
            *reinterpret_cast<float4*>(&Xs[row][c4 * 4]) =
                *reinterpret_cast<const float4*>(X + (size_t)rr * 256 + k0 + c4 * 4);
        }
        #pragma unroll
        for (int j = 0; j < 2; j++) {
            int idx = t + j * 256;
            int row = idx >> 4, c4 = idx & 15;
            *reinterpret_cast<float4*>(&Ws[row][c4 * 4]) =
                *reinterpret_cast<const float4*>(W + (size_t)(k0 + row) * NT + n0 + c4 * 4);
        }
        __syncthreads();

        #pragma unroll
        for (int ks = 0; ks < 4; ks++) {
            const int kk = ks * 8;
            unsigned bhi[4][2], blo[4][2];
            #pragma unroll
            for (int nt = 0; nt < 4; nt++) {
                int cb = warp_n * 32 + nt * 8 + lr;
                float b0 = Ws[kk + lc][cb];
                float b1 = Ws[kk + lc + 4][cb];
                bhi[nt][0] = tf32h(b0);
                bhi[nt][1] = tf32h(b1);
                blo[nt][0] = tf32h(b0 - __uint_as_float(bhi[nt][0]));
                blo[nt][1] = tf32h(b1 - __uint_as_float(bhi[nt][1]));
            }
            #pragma unroll
            for (int mt = 0; mt < 2; mt++) {
                int ar = warp_m * 32 + mt * 16 + lr;
                float a0 = Xs[ar][kk + lc];
                float a1 = Xs[ar + 8][kk + lc];
                float a2 = Xs[ar][kk + lc + 4];
                float a3 = Xs[ar + 8][kk + lc + 4];
                unsigned ah[4] = {tf32h(a0), tf32h(a1), tf32h(a2), tf32h(a3)};
                unsigned al[4] = {tf32h(a0 - __uint_as_float(ah[0])),
                                  tf32h(a1 - __uint_as_float(ah[1])),
                                  tf32h(a2 - __uint_as_float(ah[2])),
                                  tf32h(a3 - __uint_as_float(ah[3]))};
                #pragma unroll
                for (int nt = 0; nt < 4; nt++) {
                    mma_tf32(acc[mt][nt], al, bhi[nt]);
                    mma_tf32(acc[mt][nt], ah, blo[nt]);
                    mma_tf32(acc[mt][nt], ah, bhi[nt]);
                }
            }
        }
    }

    #pragma unroll
    for (int mt = 0; mt < 2; mt++) {
        #pragma unroll
        for (int nt = 0; nt < 4; nt++) {
            int row = r0 + warp_m * 32 + mt * 16 + lr;
            int colg = n0 + warp_n * 32 + nt * 8 + lc * 2;
            if (row < nrows) {
                float2 v0 = make_float2(acc[mt][nt][0], acc[mt][nt][1]);
                *reinterpret_cast<float2*>(O + (size_t)row * NT + colg) = v0;
            }
            if (row + 8 < nrows) {
                float2 v1 = make_float2(acc[mt][nt][2], acc[mt][nt][3]);
                *reinterpret_cast<float2*>(O + (size_t)(row + 8) * NT + colg) = v1;
            }
        }
    }
}

// ---------------- attention dot products ----------------
template <int H>
__global__ void k_dots(const float* __restrict__ Hm, const float* __restrict__ As,
                       const float* __restrict__ Ad, float* __restrict__ es,
                       float* __restrict__ ed) {
    const int node = blockIdx.x;
    const int w = threadIdx.x >> 5;
    const int l = threadIdx.x & 31;
    const float* hp = Hm + (size_t)node * (H * 64) + w * 64;
    float s1 = fmaf(hp[l], As[w * 64 + l], hp[l + 32] * As[w * 64 + l + 32]);
    float s2 = fmaf(hp[l], Ad[w * 64 + l], hp[l + 32] * Ad[w * 64 + l + 32]);
    #pragma unroll
    for (int o = 16; o; o >>= 1) {
        s1 += __shfl_xor_sync(0xffffffffu, s1, o);
        s2 += __shfl_xor_sync(0xffffffffu, s2, o);
    }
    if (l == 0) { es[node * H + w] = s1; ed[node * H + w] = s2; }
}

// ---------------- softmax prep: single scattered gather, head-major alpha ----------------
template <int H>
__global__ void k_prep(const float* __restrict__ es, const float* __restrict__ ed,
                       const int* __restrict__ row_ptr, const int* __restrict__ col,
                       float* __restrict__ alpha, float* __restrict__ den) {
    const int node = blockIdx.x;
    const int w = threadIdx.x >> 5;   // head
    const int l = threadIdx.x & 31;
    const int beg = row_ptr[node];
    const int end = row_ptr[node + 1];
    const float edl = ed[node * H + w];
    float* aw = alpha + (size_t)w * ETOT;

    float mm = -FLT_MAX;
    for (int c = beg + l; c < end; c += 32) {
        float e = es[col[c] * H + w] + edl;
        e = (e > 0.f) ? e : 0.2f * e;
        aw[c] = e;
        mm = fmaxf(mm, e);
    }
    #pragma unroll
    for (int o = 16; o; o >>= 1) mm = fmaxf(mm, __shfl_xor_sync(0xffffffffu, mm, o));

    float ss = 0.f;
    for (int c = beg + l; c < end; c += 32) {
        float ex = __expf(aw[c] - mm);
        aw[c] = ex;
        ss += ex;
    }
    #pragma unroll
    for (int o = 16; o; o >>= 1) ss += __shfl_xor_sync(0xffffffffu, ss, o);
    if (l == 0) den[node * H + w] = ss;
}

// ---------------- aggregation: gather-FMA, head-major alpha ----------------
template <int H, bool ELU>
__global__ void k_agg2(const float* __restrict__ Hm, const int* __restrict__ row_ptr,
                       const int* __restrict__ col, const float* __restrict__ alpha,
                       const float* __restrict__ den, const float* __restrict__ bias,
                       float* __restrict__ out) {
    constexpr int F = H * 64;
    constexpr int CH = 128;
    const int node = blockIdx.x;
    const int t = threadIdx.x;
    const int head = t >> 6;

    __shared__ int   ssrc[CH];
    __shared__ float sa[H][CH];
    __shared__ float sinv[H];

    const int beg = row_ptr[node];
    const int end = row_ptr[node + 1];

    if (t < H) sinv[t] = 1.0f / den[node * H + t];

    float a0 = 0.f, a1 = 0.f, a2 = 0.f, a3 = 0.f;
    float a4 = 0.f, a5 = 0.f, a6 = 0.f, a7 = 0.f;

    for (int ch = beg; ch < end; ch += CH) {
        const int len = min(CH, end - ch);
        __syncthreads();
        for (int i = t; i < len; i += F) ssrc[i] = col[ch + i];
        #pragma unroll
        for (int hh = 0; hh < H; hh++)
            for (int i = t; i < len; i += F)
                sa[hh][i] = alpha[(size_t)hh * ETOT + ch + i];
        __syncthreads();

        int c = 0;
        for (; c + 8 <= len; c += 8) {
            int s0 = ssrc[c],     s1 = ssrc[c + 1], s2 = ssrc[c + 2], s3 = ssrc[c + 3];
            int s4 = ssrc[c + 4], s5 = ssrc[c + 5], s6 = ssrc[c + 6], s7 = ssrc[c + 7];
            float w0 = sa[head][c],     w1 = sa[head][c + 1];
            float w2 = sa[head][c + 2], w3 = sa[head][c + 3];
            float w4 = sa[head][c + 4], w5 = sa[head][c + 5];
            float w6 = sa[head][c + 6], w7 = sa[head][c + 7];
            a0 = fmaf(Hm[(size_t)s0 * F + t], w0, a0);
            a1 = fmaf(Hm[(size_t)s1 * F + t], w1, a1);
            a2 = fmaf(Hm[(size_t)s2 * F + t], w2, a2);
            a3 = fmaf(Hm[(size_t)s3 * F + t], w3, a3);
            a4 = fmaf(Hm[(size_t)s4 * F + t], w4, a4);
            a5 = fmaf(Hm[(size_t)s5 * F + t], w5, a5);
            a6 = fmaf(Hm[(size_t)s6 * F + t], w6, a6);
            a7 = fmaf(Hm[(size_t)s7 * F + t], w7, a7);
        }
        for (; c < len; c++)
            a0 = fmaf(Hm[(size_t)ssrc[c] * F + t], sa[head][c], a0);
    }

    float res = ((a0 + a1) + (a2 + a3)) + ((a4 + a5) + (a6 + a7));
    res = res * sinv[head] + bias[t];
    if (ELU) res = (res > 0.f) ? res : expm1f(res);
    out[(size_t)node * F + t] = res;
}

// ---------------- graph embedding mean ----------------
__global__ void k_zero_f(float* __restrict__ p, int n) {
    int i = blockIdx.x * blockDim.x + threadIdx.x;
    if (i < n) p[i] = 0.f;
}

__global__ void k_mean(const float* __restrict__ node_emb, float* __restrict__ out, int n) {
    const int t = threadIdx.x;  // 64
    float a = 0.f;
    for (int r = blockIdx.x; r < n; r += gridDim.x)
        a += node_emb[(size_t)r * 64 + t];
    atomicAdd(&out[t], a * (1.0f / (float)n));
}

// ---------------- launch ----------------
extern "C" void kernel_launch(void* const* d_in, const int* in_sizes, int n_in,
                              void* d_out, int out_size) {
    const float* x   = (const float*)d_in[0];
    const int*   ei  = (const int*)d_in[1];
    const float* W1  = (const float*)d_in[2];
    const float* a1s = (const float*)d_in[3];
    const float* a1d = (const float*)d_in[4];
    const float* b1  = (const float*)d_in[5];
    const float* W2  = (const float*)d_in[6];
    const float* a2s = (const float*)d_in[7];
    const float* a2d = (const float*)d_in[8];
    const float* b2  = (const float*)d_in[9];
    const float* W3  = (const float*)d_in[10];
    const float* a3s = (const float*)d_in[11];
    const float* a3d = (const float*)d_in[12];
    const float* b3  = (const float*)d_in[13];
    float* out = (float*)d_out;

    const int n = in_sizes[0] / 16;   // 50000
    const int E = in_sizes[1] / 2;    // 800000
    const int tot = E + n;
    const int B = (n + 1023) / 1024;

    float *bufA, *bufB, *es, *ed, *den, *alpha;
    int *cnt, *cursor, *row_ptr, *col, *part;
    cudaGetSymbolAddress((void**)&bufA, g_bufA);
    cudaGetSymbolAddress((void**)&bufB, g_bufB);
    cudaGetSymbolAddress((void**)&es, g_es);
    cudaGetSymbolAddress((void**)&ed, g_ed);
    cudaGetSymbolAddress((void**)&den, g_den);
    cudaGetSymbolAddress((void**)&alpha, g_alpha);
    cudaGetSymbolAddress((void**)&cnt, g_cnt);
    cudaGetSymbolAddress((void**)&cursor, g_cursor);
    cudaGetSymbolAddress((void**)&row_ptr, g_row_ptr);
    cudaGetSymbolAddress((void**)&col, g_col_src);
    cudaGetSymbolAddress((void**)&part, g_part);

    // CSR by dst
    k_zero_int<<<(n + 255) / 256, 256>>>(cnt, n);
    k_hist<<<(tot + 255) / 256, 256>>>(ei, E, n, cnt);
    k_scan1<<<B, 1024>>>(cnt, n, row_ptr, part);
    k_scan2<<<1, 32>>>(part, B);
    k_scan3<<<B, 1024>>>(cnt, n, row_ptr, cursor, part);
    k_scatter<<<(tot + 255) / 256, 256>>>(ei, E, n, cursor, col);

    // layer 1
    k_gemm16<<<(n + 15) / 16, 256>>>(x, W1, bufA, n);
    k_dots<4><<<n, 128>>>(bufA, a1s, a1d, es, ed);
    k_prep<4><<<n, 128>>>(es, ed, row_ptr, col, alpha, den);
    k_agg2<4, true><<<n, 256>>>(bufA, row_ptr, col, alpha, den, b1, bufB);

    // layer 2 (tf32x3 tensor GEMM)
    {
        dim3 g((n + 127) / 128, 4);
        k_gemm_tf32<256><<<g, 256>>>(bufB, W2, bufA, n);
    }
    k_dots<4><<<n, 128>>>(bufA, a2s, a2d, es, ed);
    k_prep<4><<<n, 128>>>(es, ed, row_ptr, col, alpha, den);
    k_agg2<4, true><<<n, 256>>>(bufA, row_ptr, col, alpha, den, b2, bufB);

    // layer 3 (tf32x3 tensor GEMM, N=64)
    {
        dim3 g((n + 127) / 128, 1);
        k_gemm_tf32<64><<<g, 256>>>(bufB, W3, bufA, n);
    }
    k_dots<1><<<n, 32>>>(bufA, a3s, a3d, es, ed);
    k_prep<1><<<n, 32>>>(es, ed, row_ptr, col, alpha, den);
    k_agg2<1, false><<<n, 64>>>(bufA, row_ptr, col, alpha, den, b3, out);

    // graph embedding
    k_zero_f<<<1, 64>>>(out + (size_t)n * 64, 64);
    k_mean<<<256, 64>>>(out, out + (size_t)n * 64, n);
}